// round 2
// baseline (speedup 1.0000x reference)
#include <cuda_runtime.h>
#include <cuda_bf16.h>
#include <math.h>

// Problem constants
#define BB 4
#define TT 16
#define SS 256
#define DD 1024
#define HH 16
#define HKV 4
#define HD 64
#define NSEQ (BB*TT)          // 64
#define NROWS (NSEQ*SS)       // 16384
#define N_IMG 240

// Scratch (device globals: allocation-free)
__device__ float g_Q[NROWS * DD];          // 64 MB
__device__ float g_K[NROWS * HKV * HD];    // 16 MB
__device__ float g_V[NROWS * HKV * HD];    // 16 MB
__device__ float g_AO[NROWS * DD];         // 64 MB

// ---------------------------------------------------------------------------
// SGEMM: C[M,N] = A[M,K] * B[K,N], row-major, all dims multiples of tile sizes
// BM=128, BN=128, BK=8, 256 threads, 8x8 per thread
// ---------------------------------------------------------------------------
__global__ __launch_bounds__(256) void sgemm128(
    const float* __restrict__ A, const float* __restrict__ B,
    float* __restrict__ C, int M, int N, int K)
{
    const int BM = 128, BN = 128, BK = 8, TM = 8, TN = 8;
    __shared__ float As[BK * BM];   // transposed: As[k][m]
    __shared__ float Bs[BK * BN];

    const int tid  = threadIdx.x;
    const int cRow = blockIdx.y;
    const int cCol = blockIdx.x;

    A += (size_t)cRow * BM * K;
    B += (size_t)cCol * BN;
    C += (size_t)cRow * BM * N + (size_t)cCol * BN;

    const int aRow = tid >> 1;            // 0..127
    const int aCol = (tid & 1) * 4;       // 0 or 4
    const int bRow = tid >> 5;            // 0..7
    const int bCol = (tid & 31) * 4;      // 0..124
    const int tr = (tid >> 4) * TM;       // 0..120
    const int tc = (tid & 15) * TN;       // 0..120

    float acc[TM][TN];
    #pragma unroll
    for (int i = 0; i < TM; i++)
        #pragma unroll
        for (int j = 0; j < TN; j++) acc[i][j] = 0.f;

    float regM[TM], regN[TN];

    for (int k0 = 0; k0 < K; k0 += BK) {
        float4 av = *(const float4*)(A + (size_t)aRow * K + aCol);
        As[(aCol + 0) * BM + aRow] = av.x;
        As[(aCol + 1) * BM + aRow] = av.y;
        As[(aCol + 2) * BM + aRow] = av.z;
        As[(aCol + 3) * BM + aRow] = av.w;
        *(float4*)(Bs + bRow * BN + bCol) =
            *(const float4*)(B + (size_t)bRow * N + bCol);
        __syncthreads();
        A += BK;
        B += (size_t)BK * N;

        #pragma unroll
        for (int k = 0; k < BK; k++) {
            #pragma unroll
            for (int i = 0; i < TM; i += 4) {
                float4 t = *(const float4*)(As + k * BM + tr + i);
                regM[i] = t.x; regM[i+1] = t.y; regM[i+2] = t.z; regM[i+3] = t.w;
            }
            #pragma unroll
            for (int j = 0; j < TN; j += 4) {
                float4 t = *(const float4*)(Bs + k * BN + tc + j);
                regN[j] = t.x; regN[j+1] = t.y; regN[j+2] = t.z; regN[j+3] = t.w;
            }
            #pragma unroll
            for (int i = 0; i < TM; i++)
                #pragma unroll
                for (int j = 0; j < TN; j++)
                    acc[i][j] = fmaf(regM[i], regN[j], acc[i][j]);
        }
        __syncthreads();
    }

    #pragma unroll
    for (int i = 0; i < TM; i++) {
        #pragma unroll
        for (int j = 0; j < TN; j += 4) {
            float4 t = make_float4(acc[i][j], acc[i][j+1], acc[i][j+2], acc[i][j+3]);
            *(float4*)(C + (size_t)(tr + i) * N + tc + j) = t;
        }
    }
}

// ---------------------------------------------------------------------------
// RMSNorm + RoPE, in place on g_Q and g_K. One warp per 64-wide head row.
// Lane holds elements (lane) and (lane+32) == the RoPE (t1, t2) pairing.
// ---------------------------------------------------------------------------
__global__ __launch_bounds__(256) void normrope_kernel(
    const float* __restrict__ rope_cos, const float* __restrict__ rope_sin,
    const float* __restrict__ q_scale, const float* __restrict__ k_scale)
{
    const int w    = blockIdx.x * 8 + (threadIdx.x >> 5);
    const int lane = threadIdx.x & 31;

    float* ptr;
    const float* sc;
    int s;
    const int NQ = NROWS * HH;  // 262144 Q head-rows
    if (w < NQ) {
        int ns = w >> 4;        // global row
        int h  = w & 15;
        ptr = g_Q + (size_t)ns * DD + h * HD;
        s   = ns & (SS - 1);
        sc  = q_scale;
    } else {
        int r  = w - NQ;        // 0..65535
        int ns = r >> 2;
        int hk = r & 3;
        ptr = g_K + (size_t)ns * (HKV * HD) + hk * HD;
        s   = ns & (SS - 1);
        sc  = k_scale;
    }

    float a = ptr[lane];
    float b = ptr[lane + 32];
    float ssq = a * a + b * b;
    #pragma unroll
    for (int off = 16; off > 0; off >>= 1)
        ssq += __shfl_xor_sync(0xFFFFFFFFu, ssq, off);
    float r = rsqrtf(ssq * (1.0f / 64.0f) + 1e-6f);

    float an = a * r * sc[lane];
    float bn = b * r * sc[lane + 32];
    float c  = rope_cos[s * 32 + lane];
    float sn = rope_sin[s * 32 + lane];
    ptr[lane]      = an * c - bn * sn;
    ptr[lane + 32] = bn * c + an * sn;
}

// ---------------------------------------------------------------------------
// Attention: one CTA per (seq n, head h). K/V tile in smem (128 KB dynamic).
// Thread t owns query row t. Logits capped at +-50 by tanh => exp never
// overflows fp32, so no online-max needed (fixed m = 0).
// ---------------------------------------------------------------------------
__global__ __launch_bounds__(256) void attn_kernel(
    const float* __restrict__ Q, const float* __restrict__ K,
    const float* __restrict__ V, float* __restrict__ O)
{
    extern __shared__ float sm[];
    float* Ks = sm;                 // [256][64]
    float* Vs = sm + SS * HD;       // [256][64]

    const int blk = blockIdx.x;     // 0..1023
    const int n   = blk >> 4;
    const int h   = blk & 15;
    const int hk  = h >> 2;
    const int tid = threadIdx.x;

    // Cooperative coalesced load of K and V tiles (4096 float4 each)
    for (int i = 0; i < 16; i++) {
        int flat = tid + i * 256;        // 0..4095
        int j  = flat >> 4;
        int e4 = flat & 15;
        size_t goff = ((size_t)(n * SS + j) * (HKV * HD) + hk * HD) / 4 + e4;
        ((float4*)Ks)[flat] = ((const float4*)K)[goff];
        ((float4*)Vs)[flat] = ((const float4*)V)[goff];
    }
    __syncthreads();

    // q row in registers
    float4 q[16];
    const float4* qp = (const float4*)(Q + (size_t)(n * SS + tid) * DD + h * HD);
    #pragma unroll
    for (int i = 0; i < 16; i++) q[i] = qp[i];

    float4 o[16];
    #pragma unroll
    for (int i = 0; i < 16; i++) o[i] = make_float4(0.f, 0.f, 0.f, 0.f);
    float l = 0.f;

    const int jmax = (tid < N_IMG) ? N_IMG : SS;
    const float sc = 0.125f / 50.0f;     // (1/sqrt(64)) / LOGIT_CAP

    for (int j = 0; j < jmax; j++) {
        const float4* kr = (const float4*)(Ks + j * HD);
        float d0 = 0.f, d1 = 0.f, d2 = 0.f, d3 = 0.f;
        #pragma unroll
        for (int i = 0; i < 16; i++) {
            float4 kv = kr[i];
            d0 = fmaf(q[i].x, kv.x, d0);
            d1 = fmaf(q[i].y, kv.y, d1);
            d2 = fmaf(q[i].z, kv.z, d2);
            d3 = fmaf(q[i].w, kv.w, d3);
        }
        float d = (d0 + d1) + (d2 + d3);
        float sVal = 50.0f * tanhf(d * sc);
        float p = __expf(sVal);
        l += p;
        const float4* vr = (const float4*)(Vs + j * HD);
        #pragma unroll
        for (int i = 0; i < 16; i++) {
            float4 vv = vr[i];
            o[i].x = fmaf(p, vv.x, o[i].x);
            o[i].y = fmaf(p, vv.y, o[i].y);
            o[i].z = fmaf(p, vv.z, o[i].z);
            o[i].w = fmaf(p, vv.w, o[i].w);
        }
    }

    float inv = 1.0f / l;
    float4* op = (float4*)(O + (size_t)(n * SS + tid) * DD + h * HD);
    #pragma unroll
    for (int i = 0; i < 16; i++) {
        float4 t = o[i];
        op[i] = make_float4(t.x * inv, t.y * inv, t.z * inv, t.w * inv);
    }
}

// ---------------------------------------------------------------------------
extern "C" void kernel_launch(void* const* d_in, const int* in_sizes, int n_in,
                              void* d_out, int out_size)
{
    const float* x        = (const float*)d_in[0];
    // d_in[1] = attn_mask (structural; not read)
    const float* rope_cos = (const float*)d_in[2];
    const float* rope_sin = (const float*)d_in[3];
    const float* Wq       = (const float*)d_in[4];
    const float* Wk       = (const float*)d_in[5];
    const float* Wv       = (const float*)d_in[6];
    const float* Wo       = (const float*)d_in[7];
    const float* q_scale  = (const float*)d_in[8];
    const float* k_scale  = (const float*)d_in[9];
    float* out = (float*)d_out;

    float *pQ, *pK, *pV, *pAO;
    cudaGetSymbolAddress((void**)&pQ,  g_Q);
    cudaGetSymbolAddress((void**)&pK,  g_K);
    cudaGetSymbolAddress((void**)&pV,  g_V);
    cudaGetSymbolAddress((void**)&pAO, g_AO);

    // 1) Projections (fp32 SGEMM)
    sgemm128<<<dim3(DD / 128, NROWS / 128), 256>>>(x, Wq, pQ, NROWS, DD, DD);
    sgemm128<<<dim3((HKV * HD) / 128, NROWS / 128), 256>>>(x, Wk, pK, NROWS, HKV * HD, DD);
    sgemm128<<<dim3((HKV * HD) / 128, NROWS / 128), 256>>>(x, Wv, pV, NROWS, HKV * HD, DD);

    // 2) RMSNorm + RoPE (in place), 327680 warps total
    normrope_kernel<<<(NROWS * HH + NROWS * HKV) / 8, 256>>>(rope_cos, rope_sin,
                                                             q_scale, k_scale);

    // 3) Attention
    static const int ATTN_SMEM = 2 * SS * HD * (int)sizeof(float);  // 128 KB
    cudaFuncSetAttribute(attn_kernel, cudaFuncAttributeMaxDynamicSharedMemorySize,
                         ATTN_SMEM);
    attn_kernel<<<NSEQ * HH, 256, ATTN_SMEM>>>(pQ, pK, pV, pAO);

    // 4) Output projection
    sgemm128<<<dim3(DD / 128, NROWS / 128), 256>>>(pAO, Wo, out, NROWS, DD, DD);
}

// round 5
// speedup vs baseline: 1.7054x; 1.7054x over previous
#include <cuda_runtime.h>
#include <cuda_bf16.h>
#include <cstdint>
#include <math.h>

// Problem constants
#define BB 4
#define TT 16
#define SS 256
#define DD 1024
#define HH 16
#define HKV 4
#define HD 64
#define NSEQ (BB*TT)          // 64
#define NROWS (NSEQ*SS)       // 16384
#define N_IMG 240

// Scratch (device globals: allocation-free)
__device__ float g_Q[NROWS * DD];          // 64 MB
__device__ float g_K[NROWS * HKV * HD];    // 16 MB
__device__ float g_V[NROWS * HKV * HD];    // 16 MB
__device__ float g_AO[NROWS * DD];         // 64 MB

// ---------------------------------------------------------------------------
__device__ __forceinline__ float to_tf32(float x) {
    float y;
    asm("cvt.rna.tf32.f32 %0, %1;" : "=f"(y) : "f"(x));
    return y;
}

__device__ __forceinline__ void mma_tf32(float* d, const uint32_t* a, const uint32_t* b) {
    asm volatile(
        "mma.sync.aligned.m16n8k8.row.col.f32.tf32.tf32.f32 "
        "{%0,%1,%2,%3}, {%4,%5,%6,%7}, {%8,%9}, {%0,%1,%2,%3};"
        : "+f"(d[0]), "+f"(d[1]), "+f"(d[2]), "+f"(d[3])
        : "r"(a[0]), "r"(a[1]), "r"(a[2]), "r"(a[3]), "r"(b[0]), "r"(b[1]));
}

// ---------------------------------------------------------------------------
// TF32 mma.sync GEMM: C[M,N] = A[M,K] * W[K,N], all row-major.
// Tile 128x128, BK=32, 256 threads; warp tile 64x32 (4x4 of m16n8k8).
// Double-buffered smem, one sync per k-chunk, register-prefetched LDG.
// As[m][k] stride 36 (bank-conflict-free a-frags); Bs[k][n] stride 136.
// ---------------------------------------------------------------------------
#define A_STRIDE 36
#define B_STRIDE 136
#define A_SZ (128 * A_STRIDE)          // floats per buffer
#define B_SZ (32 * B_STRIDE)
#define GEMM_SMEM ((2 * (A_SZ + B_SZ)) * (int)sizeof(float))  // 71680 B

__global__ __launch_bounds__(256) void gemm_mma_tf32(
    const float* __restrict__ A, const float* __restrict__ W,
    float* __restrict__ C, int N, int K)
{
    extern __shared__ float sm[];
    float* As[2] = { sm, sm + A_SZ };
    float* Bs[2] = { sm + 2 * A_SZ, sm + 2 * A_SZ + B_SZ };

    const int tid  = threadIdx.x;
    const int wid  = tid >> 5;
    const int lane = tid & 31;
    const int grp  = lane >> 2;        // 0..7
    const int tig  = lane & 3;         // 0..3
    const int m_off = (wid & 1) * 64;  // warp m offset in tile
    const int n_off = (wid >> 1) * 32; // warp n offset in tile

    const int m0 = blockIdx.y * 128;
    const int n0 = blockIdx.x * 128;

    float acc[4][4][4];
    #pragma unroll
    for (int mt = 0; mt < 4; mt++)
        #pragma unroll
        for (int nt = 0; nt < 4; nt++)
            #pragma unroll
            for (int i = 0; i < 4; i++) acc[mt][nt][i] = 0.f;

    float4 ldA[4], ldB[4];

    // Prologue LDG (kt = 0)
    #pragma unroll
    for (int s = 0; s < 4; s++) {
        int idx = tid + s * 256;
        int am = idx >> 3, ak4 = idx & 7;
        ldA[s] = *(const float4*)(A + (size_t)(m0 + am) * K + ak4 * 4);
        int bk = idx >> 5, bn4 = idx & 31;
        ldB[s] = *(const float4*)(W + (size_t)bk * N + n0 + bn4 * 4);
    }

    const int KT = K >> 5;
    for (int kt = 0; kt < KT; kt++) {
        float* Ab = As[kt & 1];
        float* Bb = Bs[kt & 1];
        // STS with RNA tf32 rounding
        #pragma unroll
        for (int s = 0; s < 4; s++) {
            int idx = tid + s * 256;
            int am = idx >> 3, ak4 = idx & 7;
            float4 v = ldA[s];
            *(float4*)(Ab + am * A_STRIDE + ak4 * 4) = make_float4(
                to_tf32(v.x), to_tf32(v.y), to_tf32(v.z), to_tf32(v.w));
            int bk = idx >> 5, bn4 = idx & 31;
            float4 w = ldB[s];
            *(float4*)(Bb + bk * B_STRIDE + bn4 * 4) = make_float4(
                to_tf32(w.x), to_tf32(w.y), to_tf32(w.z), to_tf32(w.w));
        }
        __syncthreads();
        if (kt + 1 < KT) {
            const int kn = (kt + 1) * 32;
            #pragma unroll
            for (int s = 0; s < 4; s++) {
                int idx = tid + s * 256;
                int am = idx >> 3, ak4 = idx & 7;
                ldA[s] = *(const float4*)(A + (size_t)(m0 + am) * K + kn + ak4 * 4);
                int bk = idx >> 5, bn4 = idx & 31;
                ldB[s] = *(const float4*)(W + (size_t)(kn + bk) * N + n0 + bn4 * 4);
            }
        }
        // Compute 4 k-steps of 8
        #pragma unroll
        for (int ks = 0; ks < 4; ks++) {
            const int k = ks * 8;
            uint32_t af[4][4], bf[4][2];
            #pragma unroll
            for (int mt = 0; mt < 4; mt++) {
                const int row = m_off + mt * 16 + grp;
                af[mt][0] = __float_as_uint(Ab[row * A_STRIDE + k + tig]);
                af[mt][1] = __float_as_uint(Ab[(row + 8) * A_STRIDE + k + tig]);
                af[mt][2] = __float_as_uint(Ab[row * A_STRIDE + k + tig + 4]);
                af[mt][3] = __float_as_uint(Ab[(row + 8) * A_STRIDE + k + tig + 4]);
            }
            #pragma unroll
            for (int nt = 0; nt < 4; nt++) {
                const int col = n_off + nt * 8 + grp;
                bf[nt][0] = __float_as_uint(Bb[(k + tig) * B_STRIDE + col]);
                bf[nt][1] = __float_as_uint(Bb[(k + tig + 4) * B_STRIDE + col]);
            }
            #pragma unroll
            for (int mt = 0; mt < 4; mt++)
                #pragma unroll
                for (int nt = 0; nt < 4; nt++)
                    mma_tf32(acc[mt][nt], af[mt], bf[nt]);
        }
    }

    // Epilogue
    #pragma unroll
    for (int mt = 0; mt < 4; mt++) {
        const int row = m0 + m_off + mt * 16 + grp;
        #pragma unroll
        for (int nt = 0; nt < 4; nt++) {
            const int col = n0 + n_off + nt * 8 + 2 * tig;
            *(float2*)(C + (size_t)row * N + col) =
                make_float2(acc[mt][nt][0], acc[mt][nt][1]);
            *(float2*)(C + (size_t)(row + 8) * N + col) =
                make_float2(acc[mt][nt][2], acc[mt][nt][3]);
        }
    }
}

// ---------------------------------------------------------------------------
// RMSNorm + RoPE, in place on g_Q and g_K. One warp per 64-wide head row.
// ---------------------------------------------------------------------------
__global__ __launch_bounds__(256) void normrope_kernel(
    const float* __restrict__ rope_cos, const float* __restrict__ rope_sin,
    const float* __restrict__ q_scale, const float* __restrict__ k_scale)
{
    const int w    = blockIdx.x * 8 + (threadIdx.x >> 5);
    const int lane = threadIdx.x & 31;

    float* ptr;
    const float* sc;
    int s;
    const int NQ = NROWS * HH;
    if (w < NQ) {
        int ns = w >> 4;
        int h  = w & 15;
        ptr = g_Q + (size_t)ns * DD + h * HD;
        s   = ns & (SS - 1);
        sc  = q_scale;
    } else {
        int r  = w - NQ;
        int ns = r >> 2;
        int hk = r & 3;
        ptr = g_K + (size_t)ns * (HKV * HD) + hk * HD;
        s   = ns & (SS - 1);
        sc  = k_scale;
    }

    float a = ptr[lane];
    float b = ptr[lane + 32];
    float ssq = a * a + b * b;
    #pragma unroll
    for (int off = 16; off > 0; off >>= 1)
        ssq += __shfl_xor_sync(0xFFFFFFFFu, ssq, off);
    float r = rsqrtf(ssq * (1.0f / 64.0f) + 1e-6f);

    float an = a * r * sc[lane];
    float bn = b * r * sc[lane + 32];
    float c  = rope_cos[s * 32 + lane];
    float sn = rope_sin[s * 32 + lane];
    ptr[lane]      = an * c - bn * sn;
    ptr[lane + 32] = bn * c + an * sn;
}

// ---------------------------------------------------------------------------
// Attention: one CTA per (seq n, head h). K/V tile in smem (128 KB dynamic).
// ---------------------------------------------------------------------------
__global__ __launch_bounds__(256) void attn_kernel(
    const float* __restrict__ Q, const float* __restrict__ K,
    const float* __restrict__ V, float* __restrict__ O)
{
    extern __shared__ float sm[];
    float* Ks = sm;
    float* Vs = sm + SS * HD;

    const int blk = blockIdx.x;
    const int n   = blk >> 4;
    const int h   = blk & 15;
    const int hk  = h >> 2;
    const int tid = threadIdx.x;

    for (int i = 0; i < 16; i++) {
        int flat = tid + i * 256;
        int j  = flat >> 4;
        int e4 = flat & 15;
        size_t goff = ((size_t)(n * SS + j) * (HKV * HD) + hk * HD) / 4 + e4;
        ((float4*)Ks)[flat] = ((const float4*)K)[goff];
        ((float4*)Vs)[flat] = ((const float4*)V)[goff];
    }
    __syncthreads();

    float4 q[16];
    const float4* qp = (const float4*)(Q + (size_t)(n * SS + tid) * DD + h * HD);
    #pragma unroll
    for (int i = 0; i < 16; i++) q[i] = qp[i];

    float4 o[16];
    #pragma unroll
    for (int i = 0; i < 16; i++) o[i] = make_float4(0.f, 0.f, 0.f, 0.f);
    float l = 0.f;

    const int jmax = (tid < N_IMG) ? N_IMG : SS;
    const float sc = 0.125f / 50.0f;

    for (int j = 0; j < jmax; j++) {
        const float4* kr = (const float4*)(Ks + j * HD);
        float d0 = 0.f, d1 = 0.f, d2 = 0.f, d3 = 0.f;
        #pragma unroll
        for (int i = 0; i < 16; i++) {
            float4 kv = kr[i];
            d0 = fmaf(q[i].x, kv.x, d0);
            d1 = fmaf(q[i].y, kv.y, d1);
            d2 = fmaf(q[i].z, kv.z, d2);
            d3 = fmaf(q[i].w, kv.w, d3);
        }
        float d = (d0 + d1) + (d2 + d3);
        float sVal = 50.0f * tanhf(d * sc);
        float p = __expf(sVal);
        l += p;
        const float4* vr = (const float4*)(Vs + j * HD);
        #pragma unroll
        for (int i = 0; i < 16; i++) {
            float4 vv = vr[i];
            o[i].x = fmaf(p, vv.x, o[i].x);
            o[i].y = fmaf(p, vv.y, o[i].y);
            o[i].z = fmaf(p, vv.z, o[i].z);
            o[i].w = fmaf(p, vv.w, o[i].w);
        }
    }

    float inv = 1.0f / l;
    float4* op = (float4*)(O + (size_t)(n * SS + tid) * DD + h * HD);
    #pragma unroll
    for (int i = 0; i < 16; i++) {
        float4 t = o[i];
        op[i] = make_float4(t.x * inv, t.y * inv, t.z * inv, t.w * inv);
    }
}

// ---------------------------------------------------------------------------
extern "C" void kernel_launch(void* const* d_in, const int* in_sizes, int n_in,
                              void* d_out, int out_size)
{
    const float* x        = (const float*)d_in[0];
    // d_in[1] = attn_mask (structural; not read)
    const float* rope_cos = (const float*)d_in[2];
    const float* rope_sin = (const float*)d_in[3];
    const float* Wq       = (const float*)d_in[4];
    const float* Wk       = (const float*)d_in[5];
    const float* Wv       = (const float*)d_in[6];
    const float* Wo       = (const float*)d_in[7];
    const float* q_scale  = (const float*)d_in[8];
    const float* k_scale  = (const float*)d_in[9];
    float* out = (float*)d_out;

    float *pQ, *pK, *pV, *pAO;
    cudaGetSymbolAddress((void**)&pQ,  g_Q);
    cudaGetSymbolAddress((void**)&pK,  g_K);
    cudaGetSymbolAddress((void**)&pV,  g_V);
    cudaGetSymbolAddress((void**)&pAO, g_AO);

    cudaFuncSetAttribute(gemm_mma_tf32,
                         cudaFuncAttributeMaxDynamicSharedMemorySize, GEMM_SMEM);

    // 1) Projections (tf32 mma.sync GEMM)
    gemm_mma_tf32<<<dim3(DD / 128, NROWS / 128), 256, GEMM_SMEM>>>(x, Wq, pQ, DD, DD);
    gemm_mma_tf32<<<dim3((HKV * HD) / 128, NROWS / 128), 256, GEMM_SMEM>>>(x, Wk, pK, HKV * HD, DD);
    gemm_mma_tf32<<<dim3((HKV * HD) / 128, NROWS / 128), 256, GEMM_SMEM>>>(x, Wv, pV, HKV * HD, DD);

    // 2) RMSNorm + RoPE (in place)
    normrope_kernel<<<(NROWS * HH + NROWS * HKV) / 8, 256>>>(rope_cos, rope_sin,
                                                             q_scale, k_scale);

    // 3) Attention
    static const int ATTN_SMEM = 2 * SS * HD * (int)sizeof(float);  // 128 KB
    cudaFuncSetAttribute(attn_kernel, cudaFuncAttributeMaxDynamicSharedMemorySize,
                         ATTN_SMEM);
    attn_kernel<<<NSEQ * HH, 256, ATTN_SMEM>>>(pQ, pK, pV, pAO);

    // 4) Output projection (tf32 mma.sync GEMM)
    gemm_mma_tf32<<<dim3(DD / 128, NROWS / 128), 256, GEMM_SMEM>>>(pAO, Wo, out, DD, DD);
}